// round 1
// baseline (speedup 1.0000x reference)
#include <cuda_runtime.h>
#include <math.h>

#define IMG   512
#define NVIEW 180
#define NPIX  (IMG * IMG)

// Interleaved copy of both batch images: g_xi[y*512+x] = (batch0, batch1).
// Static __device__ scratch (no allocation).
__device__ float2 g_xi[NPIX];
// Per-view (cos, sin) as float32, computed exactly like np.cos(np.linspace(...)).astype(f32)
__device__ float2 g_trig[NVIEW];

__global__ void prep_kernel(const float* __restrict__ x) {
    int i = blockIdx.x * blockDim.x + threadIdx.x;
    if (i < NPIX) {
        g_xi[i] = make_float2(x[i], x[i + NPIX]);
    }
    if (i < NVIEW) {
        // numpy linspace(0, pi, 180, endpoint=False): theta_v = fl64(v * fl64(pi/180))
        double th = (double)i * (M_PI / 180.0);
        g_trig[i] = make_float2((float)cos(th), (float)sin(th));
    }
}

__global__ __launch_bounds__(128) void radon_kernel(float* __restrict__ out) {
    const int v    = blockIdx.y;
    const int lane = threadIdx.x & 31;
    const int warp = threadIdx.x >> 5;
    const int wi   = lane & 7;   // 8 w-lanes
    const int hi   = lane >> 3;  // 4 h-lanes
    const int w    = (blockIdx.x << 5) + (warp << 3) + wi;

    __shared__ float2 Q[IMG];    // (fl(s*gy0_h), fl(c*gy0_h))

    const float2 cs = g_trig[v];
    const float c = cs.x, s = cs.y;

    // gy0 = (2h+1)/512 - 1 = h/256 - 511/512 : exactly representable -> exact FMA
    for (int h = threadIdx.x; h < IMG; h += 128) {
        float gy0 = __fmaf_rn((float)h, 1.0f / 256.0f, -511.0f / 512.0f);
        Q[h] = make_float2(__fmul_rn(s, gy0), __fmul_rn(c, gy0));
    }
    __syncthreads();

    const float gx0 = __fmaf_rn((float)w, 1.0f / 256.0f, -511.0f / 512.0f);
    const float P = __fmul_rn(c, gx0);   // fl(c*gx0)
    const float S = __fmul_rn(s, gx0);   // fl(s*gx0)

    const float MAGIC = 12582912.0f;     // 1.5 * 2^23 (round-to-nearest-even integer trick)
    const int   MAGICI = 0x4B400000;

    float acc0 = 0.0f, acc1 = 0.0f;

    #pragma unroll 8
    for (int t = 0; t < IMG / 4; t++) {
        int h = (t << 2) + hi;
        float2 q = Q[h];
        // gx = fl(fl(c*gx0) - fl(s*gy0)); gy = fl(fl(s*gx0) + fl(c*gy0))  -- exact ref sequence
        float gx = __fsub_rn(P, q.x);
        float gy = __fadd_rn(S, q.y);
        // lower clamp required (maps to valid ix=0); upper clamp provably redundant
        gx = fmaxf(gx, -1.0f);
        gy = fmaxf(gy, -1.0f);
        float ux = __fadd_rn(gx, 1.0f);
        float uy = __fadd_rn(gy, 1.0f);
        // ((g+1)*512 - 1)*0.5 == fma(u,256,-0.5) exactly; then magic-add = rint (ties-to-even)
        float rx = __fadd_rn(__fmaf_rn(ux, 256.0f, -0.5f), MAGIC);
        float ry = __fadd_rn(__fmaf_rn(uy, 256.0f, -0.5f), MAGIC);
        int ix = __float_as_int(rx) - MAGICI;
        int iy = __float_as_int(ry) - MAGICI;
        if ((unsigned)ix < 512u && (unsigned)iy < 512u) {
            float2 val = __ldg(&g_xi[(iy << 9) + ix]);
            acc0 += val.x;
            acc1 += val.y;
        }
    }

    // combine the 4 h-lane partial sums (lanes {wi, wi+8, wi+16, wi+24})
    acc0 += __shfl_xor_sync(0xffffffffu, acc0, 8);
    acc1 += __shfl_xor_sync(0xffffffffu, acc1, 8);
    acc0 += __shfl_xor_sync(0xffffffffu, acc0, 16);
    acc1 += __shfl_xor_sync(0xffffffffu, acc1, 16);

    if (hi == 0) {
        out[v * IMG + w]                = acc0 * (1.0f / 512.0f);
        out[NVIEW * IMG + v * IMG + w]  = acc1 * (1.0f / 512.0f);
    }
}

extern "C" void kernel_launch(void* const* d_in, const int* in_sizes, int n_in,
                              void* d_out, int out_size) {
    const float* x = (const float*)d_in[0];
    float* out = (float*)d_out;

    prep_kernel<<<(NPIX + 255) / 256, 256>>>(x);

    dim3 grid(IMG / 32, NVIEW);
    radon_kernel<<<grid, 128>>>(out);
}